// round 15
// baseline (speedup 1.0000x reference)
#include <cuda_runtime.h>
#include <cuda_bf16.h>
#include <cstdint>

// ---------------- problem constants ----------------
#define NH      2048
#define NEXC    1638
#define NB      64          // B*TR batch columns
#define TS      256         // time steps
#define DTC     0.001f

#define NCTA    128
#define M_TILE  128         // rows per M-tile
#define K_CHUNK 256         // K per chunk  (16 mtiles x 8 kchunks = 128 CTAs)

// ---------------- smem layout (8x8-tile blocked, 128B per tile) ----------------
#define OFF_AHI 0
#define OFF_ALO 65536
#define OFF_BHI 131072
#define OFF_BLO 163840
#define SMEM_BYTES 196608

// ---------------- device globals (scratch; no allocs allowed) ----------------
__device__ unsigned g_flagR[NCTA][32];              // r-ready flags (128B apart)
__device__ unsigned g_flagP[NCTA][32];              // group flags (128B apart)
// rec accumulators, double-buffered per mtile; all-zero at every launch
// boundary (zero-after-read protocol preserves this across graph replays)
__device__ float g_rec[2][16][M_TILE * NB];         // 1 MB
// r double buffer, PRE-SPLIT bf16 hi/lo, stored per-chunk in the exact
// blocked-tile byte layout of the smem B region (32 KB per chunk per buf).
__device__ __nv_bfloat16 g_rhi[2][8][16384];
__device__ __nv_bfloat16 g_rlo[2][8][16384];

// ---------------- ptx helpers ----------------
__device__ __forceinline__ uint32_t smem_u32(const void* p) {
    uint32_t a;
    asm("{ .reg .u64 t; cvta.to.shared.u64 t, %1; cvt.u32.u64 %0, t; }" : "=r"(a) : "l"(p));
    return a;
}

#define LDSM4(r, a)                                                               \
    asm volatile("ldmatrix.sync.aligned.m8n8.x4.shared.b16 {%0,%1,%2,%3}, [%4];"  \
                 : "=r"((r)[0]), "=r"((r)[1]), "=r"((r)[2]), "=r"((r)[3])         \
                 : "r"(a))

#define MMA16816(c, a, b0, b1)                                                    \
    asm volatile("mma.sync.aligned.m16n8k16.row.col.f32.bf16.bf16.f32 "           \
                 "{%0,%1,%2,%3}, {%4,%5,%6,%7}, {%8,%9}, {%0,%1,%2,%3};"          \
                 : "+f"((c)[0]), "+f"((c)[1]), "+f"((c)[2]), "+f"((c)[3])         \
                 : "r"((a)[0]), "r"((a)[1]), "r"((a)[2]), "r"((a)[3]),            \
                   "r"(b0), "r"(b1))

#define CP_ASYNC16(smem_addr, gptr)                                               \
    asm volatile("cp.async.cg.shared.global [%0], [%1], 16;"                      \
                 :: "r"(smem_addr), "l"(gptr) : "memory")
#define CP_COMMIT()  asm volatile("cp.async.commit_group;" ::: "memory")
#define CP_WAIT1()   asm volatile("cp.async.wait_group 1;" ::: "memory")
#define CP_WAIT0()   asm volatile("cp.async.wait_group 0;" ::: "memory")

#define REDADD_F32(gptr, v)                                                       \
    asm volatile("red.global.add.f32 [%0], %1;" :: "l"(gptr), "f"(v) : "memory")

// ---- r-ready: each CTA arrives on its own flag; readers wait on the 16
// ---- CTAs [16*kc, 16*kc+16) that own their B k-range (mtiles 2kc, 2kc+1)
__device__ __forceinline__ void arrive_r(int cta, int tid, unsigned target) {
    __threadfence();
    __syncthreads();            // all threads' r stores fenced before flag
    if (tid == 0) {
        *(volatile unsigned*)&g_flagR[cta][0] = target;
    }
}
__device__ __forceinline__ void wait_r(int kc, int tid, unsigned target) {
    if (tid < 16) {
        volatile unsigned* p = &g_flagR[kc * 16 + tid][0];
        while ((int)(*p - target) < 0) { }
    }
    __threadfence();
    __syncthreads();
}

// ---- group barrier (8 CTAs of an mtile): 8 pollers, spread flags ----
__device__ __forceinline__ void barrier_grp(int cta, int mt, int tid, unsigned target) {
    __threadfence();
    __syncthreads();
    if (tid == 0) {
        *(volatile unsigned*)&g_flagP[cta][0] = target;
    }
    if (tid < 8) {
        volatile unsigned* p = &g_flagP[mt * 8 + tid][0];
        while ((int)(*p - target) < 0) { }
    }
    __threadfence();
    __syncthreads();
}

union Pack8 { uint4 v; __nv_bfloat16 h[8]; };
union Pack4 { uint2 v; __nv_bfloat16 h[4]; };

// writer-side split: 4 consecutive neurons (one batch row, 4 k) -> hi/lo store
__device__ __forceinline__ void write_r_split(int buf, int ck, uint32_t boff,
                                              const float* un) {
    Pack4 ph, pl;
#pragma unroll
    for (int j = 0; j < 4; j++) {
        float r = fmaxf(un[j], 0.0f);
        __nv_bfloat16 hi = __float2bfloat16(r);
        ph.h[j] = hi;
        pl.h[j] = __float2bfloat16(r - __bfloat162float(hi));
    }
    *(uint2*)((char*)&g_rhi[buf][ck][0] + boff) = ph.v;
    *(uint2*)((char*)&g_rlo[buf][ck][0] + boff) = pl.v;
}

// ---------------- main persistent kernel ----------------
__global__ void __launch_bounds__(256, 1)
rnn_kernel(
    const float* __restrict__ u0, const float* __restrict__ fs,
    const float* __restrict__ noise, const float* __restrict__ Wrec,
    const float* __restrict__ bias, float* __restrict__ out_u,
    float* __restrict__ out_du, float* __restrict__ out_eta)
{
    extern __shared__ char smem[];
    const uint32_t sbase = smem_u32(smem);
    const int tid = threadIdx.x;
    const int wid = tid >> 5;
    const int lane = tid & 31;
    const int cta = blockIdx.x;
    const int mt = cta >> 3;   // M tile 0..15
    const int kc = cta & 7;    // K chunk 0..7

    // barrier bases (own flag: equal across ALL CTAs at every launch boundary)
    const unsigned baseR = *(volatile unsigned*)&g_flagR[cta][0];
    const unsigned baseP = *(volatile unsigned*)&g_flagP[cta][0];

    // ---- eta_final copy (folded; 4KB per CTA) ----
    {
        int i = cta * (NB * NH / NCTA) + tid * 4;        // 1024 floats per CTA
        int col = i >> 11, n = i & 2047;
        float4 v = *(const float4*)(noise + (size_t)col * (TS + 1) * NH + (size_t)TS * NH + n);
        *(float4*)(out_eta + i) = v;
    }

    // ---- load + split W tile into SMEM, 8x8-blocked (once) ----
    {
        const float* wsrc = Wrec + (size_t)(mt * M_TILE) * NH + kc * K_CHUNK;
        for (int c = tid; c < M_TILE * (K_CHUNK / 8); c += 256) {   // 4096 chunks
            int row = c >> 5;
            int k0 = (c & 31) * 8;
            float4 w0 = *(const float4*)(wsrc + (size_t)row * NH + k0);
            float4 w1 = *(const float4*)(wsrc + (size_t)row * NH + k0 + 4);
            float wv[8] = {w0.x, w0.y, w0.z, w0.w, w1.x, w1.y, w1.z, w1.w};
            Pack8 ph, pl;
#pragma unroll
            for (int j = 0; j < 8; j++) {
                __nv_bfloat16 hi = __float2bfloat16(wv[j]);
                ph.h[j] = hi;
                pl.h[j] = __float2bfloat16(wv[j] - __bfloat162float(hi));
            }
            // A tile layout: tile(m>>3, k>>3) at ((m>>3)*32 + (k>>3))*128, row (m&7)*16
            uint32_t off = (uint32_t)((row >> 3) * 32 + (k0 >> 3)) * 128u + (uint32_t)(row & 7) * 16u;
            *(uint4*)(smem + OFF_AHI + off) = ph.v;
            *(uint4*)(smem + OFF_ALO + off) = pl.v;
        }
    }

    // ---- per-thread state (mapping A: col = tid/4, 4 consecutive n) ----
    const int colA = tid >> 2;
    const int n0A = mt * M_TILE + kc * 16 + (tid & 3) * 4;
    // writer-side split target: chunk + byte offset in blocked layout
    const int wck = n0A >> 8;                       // chunk 0..7
    const int wlk = n0A & 255;                      // local k (4 consecutive)
    const uint32_t wboff = (uint32_t)(((wlk >> 3) * 8 + (colA >> 3)) * 128
                                      + (colA & 7) * 16 + (wlk & 7) * 2);
    float u[4], bs[4], tinv[4];
    {
        float4 t4 = *(const float4*)(u0 + (size_t)colA * NH + n0A);
        u[0] = t4.x; u[1] = t4.y; u[2] = t4.z; u[3] = t4.w;
        float4 b4 = *(const float4*)(bias + n0A);
        bs[0] = b4.x; bs[1] = b4.y; bs[2] = b4.z; bs[3] = b4.w;
#pragma unroll
        for (int j = 0; j < 4; j++) tinv[j] = (n0A + j < NEXC) ? 50.0f : 100.0f;
    }
    write_r_split(0, wck, wboff, u);   // r(0) = relu(u0)  (split applies relu)

    arrive_r(cta, tid, baseR + 1);     // r(0) published

    // ---- per-lane ldmatrix base addresses ----
    const uint32_t aOffL = (uint32_t)((wid * 2 + ((lane >> 3) & 1)) * 4096
                                      + (lane >> 4) * 128 + (lane & 7) * 16);
    const uint32_t aAhi = sbase + OFF_AHI + aOffL;
    const uint32_t aAlo = sbase + OFF_ALO + aOffL;
    const uint32_t bOffL = (uint32_t)(((lane >> 3) & 1) * 1024
                                      + (lane >> 4) * 128 + (lane & 7) * 16);
    const uint32_t aBhi = sbase + OFF_BHI + bOffL;
    const uint32_t aBlo = sbase + OFF_BLO + bOffL;

    // rec accumulator addresses: atomics target (own partial rows), read target
    // (own 16-row slice kc*16..kc*16+16)
    float* recbuf[2] = { &g_rec[0][mt][0], &g_rec[1][mt][0] };
    const int accRow0 = wid * 16 + (lane >> 2);     // partial row for acc[]
    const int accCol = (lane & 3) * 2;

    // ---- A-hi fragments: resident in registers for the whole run ----
    uint32_t ahreg[16][4];
#pragma unroll
    for (int ks = 0; ks < 16; ks++)
        LDSM4(ahreg[ks], aAhi + (uint32_t)ks * 256u);

    for (int t = 0; t < TS; t++) {
        const int pb = t & 1;

        // prefetch fs / noise for this step (independent of r; issue before wait)
        float4 f4 = *(const float4*)(fs + ((size_t)colA * TS + t) * NH + n0A);
        float4 e4 = *(const float4*)(noise + ((size_t)colA * (TS + 1) + t) * NH + n0A);

        // ---- wait only for the 16 CTAs owning our B k-range ----
        wait_r(kc, tid, baseR + t + 1);

        // ---- B tiles: staged async copy (pre-split, pre-blocked in global) ----
        {
            const char* srcH = (const char*)&g_rhi[pb][kc][0];
            const char* srcL = (const char*)&g_rlo[pb][kc][0];
            // stage 0: first 16KB of each region (k-steps 0..7)
#pragma unroll
            for (int i = 0; i < 4; i++) {
                uint32_t off = (uint32_t)(tid + i * 256) * 16u;
                CP_ASYNC16(sbase + OFF_BHI + off, srcH + off);
                CP_ASYNC16(sbase + OFF_BLO + off, srcL + off);
            }
            CP_COMMIT();
            // stage 1: second 16KB of each region (k-steps 8..15)
#pragma unroll
            for (int i = 4; i < 8; i++) {
                uint32_t off = (uint32_t)(tid + i * 256) * 16u;
                CP_ASYNC16(sbase + OFF_BHI + off, srcH + off);
                CP_ASYNC16(sbase + OFF_BLO + off, srcL + off);
            }
            CP_COMMIT();
        }
        CP_WAIT1();          // stage 0 resident
        __syncthreads();

        // ---- GEMM: 16 k-steps, 8 n-frags, 3-pass split-bf16 (A-hi from regs) ----
        float acc[32];
#pragma unroll
        for (int i = 0; i < 32; i++) acc[i] = 0.0f;

#pragma unroll
        for (int ks = 0; ks < 8; ks++) {
            uint32_t al[4];
            LDSM4(al, aAlo + (uint32_t)ks * 256u);
#pragma unroll
            for (int nf2 = 0; nf2 < 4; nf2++) {
                uint32_t bh[4], bl[4];
                LDSM4(bh, aBhi + (uint32_t)ks * 2048u + (uint32_t)nf2 * 256u);
                LDSM4(bl, aBlo + (uint32_t)ks * 2048u + (uint32_t)nf2 * 256u);
                float* c0 = acc + (nf2 * 2) * 4;
                float* c1 = acc + (nf2 * 2 + 1) * 4;
                MMA16816(c0, ahreg[ks], bh[0], bh[1]);
                MMA16816(c1, ahreg[ks], bh[2], bh[3]);
                MMA16816(c0, ahreg[ks], bl[0], bl[1]);
                MMA16816(c1, ahreg[ks], bl[2], bl[3]);
                MMA16816(c0, al, bh[0], bh[1]);
                MMA16816(c1, al, bh[2], bh[3]);
            }
        }

        CP_WAIT0();          // stage 1 resident
        __syncthreads();

#pragma unroll
        for (int ks = 8; ks < 16; ks++) {
            uint32_t al[4];
            LDSM4(al, aAlo + (uint32_t)ks * 256u);
#pragma unroll
            for (int nf2 = 0; nf2 < 4; nf2++) {
                uint32_t bh[4], bl[4];
                LDSM4(bh, aBhi + (uint32_t)ks * 2048u + (uint32_t)nf2 * 256u);
                LDSM4(bl, aBlo + (uint32_t)ks * 2048u + (uint32_t)nf2 * 256u);
                float* c0 = acc + (nf2 * 2) * 4;
                float* c1 = acc + (nf2 * 2 + 1) * 4;
                MMA16816(c0, ahreg[ks], bh[0], bh[1]);
                MMA16816(c1, ahreg[ks], bh[2], bh[3]);
                MMA16816(c0, ahreg[ks], bl[0], bl[1]);
                MMA16816(c1, ahreg[ks], bl[2], bl[3]);
                MMA16816(c0, al, bh[0], bh[1]);
                MMA16816(c1, al, bh[2], bh[3]);
            }
        }

        // ---- reduce partials via non-returning global atomics ----
        {
            float* rdst = recbuf[pb];
#pragma unroll
            for (int nf = 0; nf < 8; nf++) {
                int c0 = nf * 8 + accCol;
                REDADD_F32(rdst + accRow0 * NB + c0,       acc[nf * 4 + 0]);
                REDADD_F32(rdst + accRow0 * NB + c0 + 1,   acc[nf * 4 + 1]);
                REDADD_F32(rdst + (accRow0 + 8) * NB + c0,     acc[nf * 4 + 2]);
                REDADD_F32(rdst + (accRow0 + 8) * NB + c0 + 1, acc[nf * 4 + 3]);
            }
        }

        barrier_grp(cta, mt, tid, baseP + t + 1);   // mtile group: rec complete

        // ---- pointwise update (read own rec slice, zero it, write r split) ----
        {
            float fv[4] = {f4.x, f4.y, f4.z, f4.w};
            float ev[4] = {e4.x, e4.y, e4.z, e4.w};
            float rec[4], du[4], un[4];
            float* rsl = recbuf[pb] + (kc * 16 + (tid & 3) * 4) * NB + colA;
#pragma unroll
            for (int j = 0; j < 4; j++)
                rec[j] = __ldcg(rsl + j * NB);
#pragma unroll
            for (int j = 0; j < 4; j++)
                __stcg(rsl + j * NB, 0.0f);      // restore zero for reuse at t+2
#pragma unroll
            for (int j = 0; j < 4; j++) {
                du[j] = (-u[j] + fv[j] + rec[j] + bs[j] + ev[j]) * tinv[j];
                un[j] = u[j] + du[j] * DTC;
                un[j] = fminf(5.0f, fmaxf(-5.0f, un[j]));
            }
            write_r_split((t + 1) & 1, wck, wboff, un);

            arrive_r(cta, tid, baseR + t + 2);   // r(t+1) published ASAP

            // deferred output stores (off the critical path)
            float* ou = out_u + ((size_t)colA * TS + t) * NH + n0A;
            float* od = out_du + ((size_t)colA * TS + t) * NH + n0A;
            *(float4*)ou = make_float4(un[0], un[1], un[2], un[3]);
            *(float4*)od = make_float4(du[0], du[1], du[2], du[3]);
            u[0] = un[0]; u[1] = un[1]; u[2] = un[2]; u[3] = un[3];
        }
    }
}

extern "C" void kernel_launch(void* const* d_in, const int* in_sizes, int n_in,
                              void* d_out, int out_size) {
    const float* u0    = (const float*)d_in[0];
    const float* fs    = (const float*)d_in[1];
    const float* noise = (const float*)d_in[2];
    const float* Wrec  = (const float*)d_in[3];
    const float* bias  = (const float*)d_in[4];
    float* out = (float*)d_out;
    float* out_u   = out;                       // 64*256*2048
    float* out_eta = out + 33554432;            // 64*2048
    float* out_du  = out + 33554432 + 131072;

    cudaFuncSetAttribute(rnn_kernel, cudaFuncAttributeMaxDynamicSharedMemorySize, SMEM_BYTES);
    rnn_kernel<<<NCTA, 256, SMEM_BYTES>>>(u0, fs, noise, Wrec, bias, out_u, out_du, out_eta);
}

// round 16
// speedup vs baseline: 1.1437x; 1.1437x over previous
#include <cuda_runtime.h>
#include <cuda_bf16.h>
#include <cstdint>

// ---------------- problem constants ----------------
#define NH      2048
#define NEXC    1638
#define NB      64          // B*TR batch columns
#define TS      256         // time steps
#define DTC     0.001f

#define NCTA    128
#define M_TILE  128         // rows per M-tile
#define K_CHUNK 256         // K per chunk  (16 mtiles x 8 kchunks = 128 CTAs)

// ---------------- smem layout (8x8-tile blocked, 128B per tile) ----------------
#define OFF_AHI 0
#define OFF_ALO 65536
#define OFF_BHI 131072
#define OFF_BLO 163840
#define OFF_REC 196608                 // 16 x 68 floats = 4352 B
#define SMEM_BYTES 201088

// ---------------- device globals (scratch; no allocs allowed) ----------------
__device__ unsigned g_flagR[NCTA][32];              // r-ready flags (128B apart)
__device__ unsigned g_flagP[NCTA][32];              // group flags (128B apart)
__device__ float g_partial[NCTA * M_TILE * NB];     // 4 MB
// r double buffer, PRE-SPLIT bf16 hi/lo, stored per-chunk in the exact
// blocked-tile byte layout of the smem B region (32 KB per chunk per buf).
__device__ __nv_bfloat16 g_rhi[2][8][16384];
__device__ __nv_bfloat16 g_rlo[2][8][16384];

// ---------------- ptx helpers ----------------
__device__ __forceinline__ uint32_t smem_u32(const void* p) {
    uint32_t a;
    asm("{ .reg .u64 t; cvta.to.shared.u64 t, %1; cvt.u32.u64 %0, t; }" : "=r"(a) : "l"(p));
    return a;
}

#define LDSM4(r, a)                                                               \
    asm volatile("ldmatrix.sync.aligned.m8n8.x4.shared.b16 {%0,%1,%2,%3}, [%4];"  \
                 : "=r"((r)[0]), "=r"((r)[1]), "=r"((r)[2]), "=r"((r)[3])         \
                 : "r"(a))

#define MMA16816(c, a, b0, b1)                                                    \
    asm volatile("mma.sync.aligned.m16n8k16.row.col.f32.bf16.bf16.f32 "           \
                 "{%0,%1,%2,%3}, {%4,%5,%6,%7}, {%8,%9}, {%0,%1,%2,%3};"          \
                 : "+f"((c)[0]), "+f"((c)[1]), "+f"((c)[2]), "+f"((c)[3])         \
                 : "r"((a)[0]), "r"((a)[1]), "r"((a)[2]), "r"((a)[3]),            \
                   "r"(b0), "r"(b1))

#define CP_ASYNC16(smem_addr, gptr)                                               \
    asm volatile("cp.async.cg.shared.global [%0], [%1], 16;"                      \
                 :: "r"(smem_addr), "l"(gptr) : "memory")
#define CP_COMMIT()  asm volatile("cp.async.commit_group;" ::: "memory")
#define CP_WAIT1()   asm volatile("cp.async.wait_group 1;" ::: "memory")
#define CP_WAIT0()   asm volatile("cp.async.wait_group 0;" ::: "memory")

// ---- r-ready: each CTA arrives on its own flag; readers wait on the 16
// ---- CTAs [16*kc, 16*kc+16) that own their B k-range (mtiles 2kc, 2kc+1)
__device__ __forceinline__ void arrive_r(int cta, int tid, unsigned target) {
    __threadfence();
    __syncthreads();            // all threads' r stores fenced before flag
    if (tid == 0) {
        *(volatile unsigned*)&g_flagR[cta][0] = target;
    }
}
__device__ __forceinline__ void wait_r(int kc, int tid, unsigned target) {
    if (tid < 16) {
        volatile unsigned* p = &g_flagR[kc * 16 + tid][0];
        while ((int)(*p - target) < 0) { }
    }
    __threadfence();
    __syncthreads();
}

// ---- group barrier (8 CTAs of an mtile): 8 pollers, spread flags ----
__device__ __forceinline__ void barrier_grp(int cta, int mt, int tid, unsigned target) {
    __threadfence();
    __syncthreads();
    if (tid == 0) {
        *(volatile unsigned*)&g_flagP[cta][0] = target;
    }
    if (tid < 8) {
        volatile unsigned* p = &g_flagP[mt * 8 + tid][0];
        while ((int)(*p - target) < 0) { }
    }
    __threadfence();
    __syncthreads();
}

union Pack8 { uint4 v; __nv_bfloat16 h[8]; };
union Pack4 { uint2 v; __nv_bfloat16 h[4]; };

// writer-side split: 4 consecutive neurons (one batch row, 4 k) -> hi/lo store
__device__ __forceinline__ void write_r_split(int buf, int ck, uint32_t boff,
                                              const float* un) {
    Pack4 ph, pl;
#pragma unroll
    for (int j = 0; j < 4; j++) {
        float r = fmaxf(un[j], 0.0f);
        __nv_bfloat16 hi = __float2bfloat16(r);
        ph.h[j] = hi;
        pl.h[j] = __float2bfloat16(r - __bfloat162float(hi));
    }
    *(uint2*)((char*)&g_rhi[buf][ck][0] + boff) = ph.v;
    *(uint2*)((char*)&g_rlo[buf][ck][0] + boff) = pl.v;
}

// ---------------- main persistent kernel ----------------
__global__ void __launch_bounds__(256, 1)
rnn_kernel(
    const float* __restrict__ u0, const float* __restrict__ fs,
    const float* __restrict__ noise, const float* __restrict__ Wrec,
    const float* __restrict__ bias, float* __restrict__ out_u,
    float* __restrict__ out_du, float* __restrict__ out_eta)
{
    extern __shared__ char smem[];
    const uint32_t sbase = smem_u32(smem);
    const int tid = threadIdx.x;
    const int wid = tid >> 5;
    const int lane = tid & 31;
    const int cta = blockIdx.x;
    const int mt = cta >> 3;   // M tile 0..15
    const int kc = cta & 7;    // K chunk 0..7

    // barrier bases (own flag: equal across ALL CTAs at every launch boundary)
    const unsigned baseR = *(volatile unsigned*)&g_flagR[cta][0];
    const unsigned baseP = *(volatile unsigned*)&g_flagP[cta][0];

    // ---- eta_final copy (folded; 4KB per CTA) ----
    {
        int i = cta * (NB * NH / NCTA) + tid * 4;        // 1024 floats per CTA
        int col = i >> 11, n = i & 2047;
        float4 v = *(const float4*)(noise + (size_t)col * (TS + 1) * NH + (size_t)TS * NH + n);
        *(float4*)(out_eta + i) = v;
    }

    // ---- load + split W tile into SMEM, 8x8-blocked (once) ----
    {
        const float* wsrc = Wrec + (size_t)(mt * M_TILE) * NH + kc * K_CHUNK;
        for (int c = tid; c < M_TILE * (K_CHUNK / 8); c += 256) {   // 4096 chunks
            int row = c >> 5;
            int k0 = (c & 31) * 8;
            float4 w0 = *(const float4*)(wsrc + (size_t)row * NH + k0);
            float4 w1 = *(const float4*)(wsrc + (size_t)row * NH + k0 + 4);
            float wv[8] = {w0.x, w0.y, w0.z, w0.w, w1.x, w1.y, w1.z, w1.w};
            Pack8 ph, pl;
#pragma unroll
            for (int j = 0; j < 8; j++) {
                __nv_bfloat16 hi = __float2bfloat16(wv[j]);
                ph.h[j] = hi;
                pl.h[j] = __float2bfloat16(wv[j] - __bfloat162float(hi));
            }
            // A tile layout: tile(m>>3, k>>3) at ((m>>3)*32 + (k>>3))*128, row (m&7)*16
            uint32_t off = (uint32_t)((row >> 3) * 32 + (k0 >> 3)) * 128u + (uint32_t)(row & 7) * 16u;
            *(uint4*)(smem + OFF_AHI + off) = ph.v;
            *(uint4*)(smem + OFF_ALO + off) = pl.v;
        }
    }

    // ---- per-thread state (mapping A: col = tid/4, 4 consecutive n) ----
    const int colA = tid >> 2;
    const int n0A = mt * M_TILE + kc * 16 + (tid & 3) * 4;
    // writer-side split target: chunk + byte offset in blocked layout
    const int wck = n0A >> 8;                       // chunk 0..7
    const int wlk = n0A & 255;                      // local k (4 consecutive)
    const uint32_t wboff = (uint32_t)(((wlk >> 3) * 8 + (colA >> 3)) * 128
                                      + (colA & 7) * 16 + (wlk & 7) * 2);
    float u[4], bs[4], tinv[4];
    {
        float4 t4 = *(const float4*)(u0 + (size_t)colA * NH + n0A);
        u[0] = t4.x; u[1] = t4.y; u[2] = t4.z; u[3] = t4.w;
        float4 b4 = *(const float4*)(bias + n0A);
        bs[0] = b4.x; bs[1] = b4.y; bs[2] = b4.z; bs[3] = b4.w;
#pragma unroll
        for (int j = 0; j < 4; j++) tinv[j] = (n0A + j < NEXC) ? 50.0f : 100.0f;
    }
    write_r_split(0, wck, wboff, u);   // r(0) = relu(u0)  (split applies relu)

    arrive_r(cta, tid, baseR + 1);     // r(0) published

    // ---- per-lane ldmatrix base addresses ----
    const uint32_t aOffL = (uint32_t)((wid * 2 + ((lane >> 3) & 1)) * 4096
                                      + (lane >> 4) * 128 + (lane & 7) * 16);
    const uint32_t aAhi = sbase + OFF_AHI + aOffL;
    const uint32_t aAlo = sbase + OFF_ALO + aOffL;
    const uint32_t bOffL = (uint32_t)(((lane >> 3) & 1) * 1024
                                      + (lane >> 4) * 128 + (lane & 7) * 16);
    const uint32_t aBhi = sbase + OFF_BHI + bOffL;
    const uint32_t aBlo = sbase + OFF_BLO + bOffL;

    // ---- A-hi fragments: resident in registers for the whole run ----
    uint32_t ahreg[16][4];
#pragma unroll
    for (int ks = 0; ks < 16; ks++)
        LDSM4(ahreg[ks], aAhi + (uint32_t)ks * 256u);

    for (int t = 0; t < TS; t++) {
        const int pb = t & 1;

        // prefetch fs / noise for this step (independent of r; issue before wait)
        float4 f4 = *(const float4*)(fs + ((size_t)colA * TS + t) * NH + n0A);
        float4 e4 = *(const float4*)(noise + ((size_t)colA * (TS + 1) + t) * NH + n0A);

        // ---- wait only for the 16 CTAs owning our B k-range ----
        wait_r(kc, tid, baseR + t + 1);

        // ---- B tiles: staged async copy (pre-split, pre-blocked in global) ----
        {
            const char* srcH = (const char*)&g_rhi[pb][kc][0];
            const char* srcL = (const char*)&g_rlo[pb][kc][0];
            // stage 0: first 16KB of each region (k-steps 0..7)
#pragma unroll
            for (int i = 0; i < 4; i++) {
                uint32_t off = (uint32_t)(tid + i * 256) * 16u;
                CP_ASYNC16(sbase + OFF_BHI + off, srcH + off);
                CP_ASYNC16(sbase + OFF_BLO + off, srcL + off);
            }
            CP_COMMIT();
            // stage 1: second 16KB of each region (k-steps 8..15)
#pragma unroll
            for (int i = 4; i < 8; i++) {
                uint32_t off = (uint32_t)(tid + i * 256) * 16u;
                CP_ASYNC16(sbase + OFF_BHI + off, srcH + off);
                CP_ASYNC16(sbase + OFF_BLO + off, srcL + off);
            }
            CP_COMMIT();
        }
        CP_WAIT1();          // stage 0 resident
        __syncthreads();

        // ---- GEMM: 16 k-steps, 8 n-frags, 3-pass split-bf16 (A-hi from regs) ----
        float acc[32];
#pragma unroll
        for (int i = 0; i < 32; i++) acc[i] = 0.0f;

#pragma unroll
        for (int ks = 0; ks < 8; ks++) {
            uint32_t al[4];
            LDSM4(al, aAlo + (uint32_t)ks * 256u);
#pragma unroll
            for (int nf2 = 0; nf2 < 4; nf2++) {
                uint32_t bh[4], bl[4];
                LDSM4(bh, aBhi + (uint32_t)ks * 2048u + (uint32_t)nf2 * 256u);
                LDSM4(bl, aBlo + (uint32_t)ks * 2048u + (uint32_t)nf2 * 256u);
                float* c0 = acc + (nf2 * 2) * 4;
                float* c1 = acc + (nf2 * 2 + 1) * 4;
                MMA16816(c0, ahreg[ks], bh[0], bh[1]);
                MMA16816(c1, ahreg[ks], bh[2], bh[3]);
                MMA16816(c0, ahreg[ks], bl[0], bl[1]);
                MMA16816(c1, ahreg[ks], bl[2], bl[3]);
                MMA16816(c0, al, bh[0], bh[1]);
                MMA16816(c1, al, bh[2], bh[3]);
            }
        }

        CP_WAIT0();          // stage 1 resident
        __syncthreads();

#pragma unroll
        for (int ks = 8; ks < 16; ks++) {
            uint32_t al[4];
            LDSM4(al, aAlo + (uint32_t)ks * 256u);
#pragma unroll
            for (int nf2 = 0; nf2 < 4; nf2++) {
                uint32_t bh[4], bl[4];
                LDSM4(bh, aBhi + (uint32_t)ks * 2048u + (uint32_t)nf2 * 256u);
                LDSM4(bl, aBlo + (uint32_t)ks * 2048u + (uint32_t)nf2 * 256u);
                float* c0 = acc + (nf2 * 2) * 4;
                float* c1 = acc + (nf2 * 2 + 1) * 4;
                MMA16816(c0, ahreg[ks], bh[0], bh[1]);
                MMA16816(c1, ahreg[ks], bh[2], bh[3]);
                MMA16816(c0, ahreg[ks], bl[0], bl[1]);
                MMA16816(c1, ahreg[ks], bl[2], bl[3]);
                MMA16816(c0, al, bh[0], bh[1]);
                MMA16816(c1, al, bh[2], bh[3]);
            }
        }

        // ---- store partials to global ----
        {
            float* pdst = g_partial + (size_t)cta * (M_TILE * NB);
            int r0 = wid * 16 + (lane >> 2);
            int cc = (lane & 3) * 2;
#pragma unroll
            for (int nf = 0; nf < 8; nf++) {
                *(float2*)(pdst + (size_t)r0 * NB + nf * 8 + cc) =
                    make_float2(acc[nf * 4 + 0], acc[nf * 4 + 1]);
                *(float2*)(pdst + (size_t)(r0 + 8) * NB + nf * 8 + cc) =
                    make_float2(acc[nf * 4 + 2], acc[nf * 4 + 3]);
            }
        }

        barrier_grp(cta, mt, tid, baseP + t + 1);   // mtile group: partials ready

        // ---- reduce 8 partials -> rec tile in SMEM ----
        {
            int mB = tid >> 4;            // 0..15 local row
            int cB = (tid & 15) * 4;      // col base
            float4 acc4 = make_float4(0.f, 0.f, 0.f, 0.f);
#pragma unroll
            for (int k2 = 0; k2 < 8; k2++) {
                float4 v = __ldcg((const float4*)(g_partial +
                    ((size_t)(mt * 8 + k2) * M_TILE + kc * 16 + mB) * NB + cB));
                acc4.x += v.x; acc4.y += v.y; acc4.z += v.z; acc4.w += v.w;
            }
            *(float4*)(smem + OFF_REC + (size_t)(mB * 68 + cB) * 4) = acc4;
        }
        __syncthreads();

        // ---- pointwise update (r split published before output stores) ----
        {
            float fv[4] = {f4.x, f4.y, f4.z, f4.w};
            float ev[4] = {e4.x, e4.y, e4.z, e4.w};
            float rec[4], du[4], un[4];
#pragma unroll
            for (int j = 0; j < 4; j++)
                rec[j] = *(const float*)(smem + OFF_REC +
                            (size_t)(((tid & 3) * 4 + j) * 68 + colA) * 4);
#pragma unroll
            for (int j = 0; j < 4; j++) {
                du[j] = (-u[j] + fv[j] + rec[j] + bs[j] + ev[j]) * tinv[j];
                un[j] = u[j] + du[j] * DTC;
                un[j] = fminf(5.0f, fmaxf(-5.0f, un[j]));
            }
            write_r_split((t + 1) & 1, wck, wboff, un);

            arrive_r(cta, tid, baseR + t + 2);   // r(t+1) published ASAP

            // deferred output stores (off the critical path)
            float* ou = out_u + ((size_t)colA * TS + t) * NH + n0A;
            float* od = out_du + ((size_t)colA * TS + t) * NH + n0A;
            *(float4*)ou = make_float4(un[0], un[1], un[2], un[3]);
            *(float4*)od = make_float4(du[0], du[1], du[2], du[3]);
            u[0] = un[0]; u[1] = un[1]; u[2] = un[2]; u[3] = un[3];
        }
    }
}

extern "C" void kernel_launch(void* const* d_in, const int* in_sizes, int n_in,
                              void* d_out, int out_size) {
    const float* u0    = (const float*)d_in[0];
    const float* fs    = (const float*)d_in[1];
    const float* noise = (const float*)d_in[2];
    const float* Wrec  = (const float*)d_in[3];
    const float* bias  = (const float*)d_in[4];
    float* out = (float*)d_out;
    float* out_u   = out;                       // 64*256*2048
    float* out_eta = out + 33554432;            // 64*2048
    float* out_du  = out + 33554432 + 131072;

    cudaFuncSetAttribute(rnn_kernel, cudaFuncAttributeMaxDynamicSharedMemorySize, SMEM_BYTES);
    rnn_kernel<<<NCTA, 256, SMEM_BYTES>>>(u0, fs, noise, Wrec, bias, out_u, out_du, out_eta);
}

// round 17
// speedup vs baseline: 1.1765x; 1.0287x over previous
#include <cuda_runtime.h>
#include <cuda_bf16.h>
#include <cstdint>

// ---------------- problem constants ----------------
#define NH      2048
#define NEXC    1638
#define NB      64          // B*TR batch columns
#define TS      256         // time steps
#define DTC     0.001f

#define NCTA    128
#define M_TILE  128         // rows per M-tile
#define K_CHUNK 256         // K per chunk  (16 mtiles x 8 kchunks = 128 CTAs)

// ---------------- smem layout (8x8-tile blocked, 128B per tile) ----------------
#define OFF_AHI 0
#define OFF_ALO 65536
#define OFF_BHI 131072
#define OFF_BLO 163840
#define OFF_REC 196608                 // 16 x 68 floats = 4352 B
#define SMEM_BYTES 201088

// ---------------- device globals (scratch; no allocs allowed) ----------------
__device__ unsigned g_flagR[NCTA][32];              // r-ready flags (128B apart)
__device__ unsigned g_flagP[NCTA][32];              // group flags (128B apart)
__device__ float g_partial[NCTA * M_TILE * NB];     // 4 MB
// r double buffer, PRE-SPLIT bf16 hi/lo, stored per-chunk in the exact
// blocked-tile byte layout of the smem B region (32 KB per chunk per buf).
__device__ __nv_bfloat16 g_rhi[2][8][16384];
__device__ __nv_bfloat16 g_rlo[2][8][16384];

// ---------------- ptx helpers ----------------
__device__ __forceinline__ uint32_t smem_u32(const void* p) {
    uint32_t a;
    asm("{ .reg .u64 t; cvta.to.shared.u64 t, %1; cvt.u32.u64 %0, t; }" : "=r"(a) : "l"(p));
    return a;
}

__device__ __forceinline__ unsigned ld_acq(const unsigned* p) {
    unsigned v;
    asm volatile("ld.acquire.gpu.global.u32 %0, [%1];" : "=r"(v) : "l"(p) : "memory");
    return v;
}

#define LDSM4(r, a)                                                               \
    asm volatile("ldmatrix.sync.aligned.m8n8.x4.shared.b16 {%0,%1,%2,%3}, [%4];"  \
                 : "=r"((r)[0]), "=r"((r)[1]), "=r"((r)[2]), "=r"((r)[3])         \
                 : "r"(a))

#define MMA16816(c, a, b0, b1)                                                    \
    asm volatile("mma.sync.aligned.m16n8k16.row.col.f32.bf16.bf16.f32 "           \
                 "{%0,%1,%2,%3}, {%4,%5,%6,%7}, {%8,%9}, {%0,%1,%2,%3};"          \
                 : "+f"((c)[0]), "+f"((c)[1]), "+f"((c)[2]), "+f"((c)[3])         \
                 : "r"((a)[0]), "r"((a)[1]), "r"((a)[2]), "r"((a)[3]),            \
                   "r"(b0), "r"(b1))

#define CP_ASYNC16(smem_addr, gptr)                                               \
    asm volatile("cp.async.cg.shared.global [%0], [%1], 16;"                      \
                 :: "r"(smem_addr), "l"(gptr) : "memory")
#define CP_COMMIT()  asm volatile("cp.async.commit_group;" ::: "memory")
#define CP_WAIT1()   asm volatile("cp.async.wait_group 1;" ::: "memory")
#define CP_WAIT0()   asm volatile("cp.async.wait_group 0;" ::: "memory")

// ---- r-ready arrive: each CTA publishes its own flag after its r stores ----
__device__ __forceinline__ void arrive_r(int cta, int tid, unsigned target) {
    __threadfence();
    __syncthreads();            // all threads' r stores fenced before flag
    if (tid == 0) {
        *(volatile unsigned*)&g_flagR[cta][0] = target;
    }
}

// ---- group barrier (8 CTAs of an mtile): 8 pollers, spread flags ----
__device__ __forceinline__ void barrier_grp(int cta, int mt, int tid, unsigned target) {
    __threadfence();
    __syncthreads();
    if (tid == 0) {
        *(volatile unsigned*)&g_flagP[cta][0] = target;
    }
    if (tid < 8) {
        volatile unsigned* p = &g_flagP[mt * 8 + tid][0];
        while ((int)(*p - target) < 0) { }
    }
    __threadfence();
    __syncthreads();
}

union Pack8 { uint4 v; __nv_bfloat16 h[8]; };
union Pack4 { uint2 v; __nv_bfloat16 h[4]; };

// writer-side split: 4 consecutive neurons (one batch row, 4 k) -> hi/lo store
__device__ __forceinline__ void write_r_split(int buf, int ck, uint32_t boff,
                                              const float* un) {
    Pack4 ph, pl;
#pragma unroll
    for (int j = 0; j < 4; j++) {
        float r = fmaxf(un[j], 0.0f);
        __nv_bfloat16 hi = __float2bfloat16(r);
        ph.h[j] = hi;
        pl.h[j] = __float2bfloat16(r - __bfloat162float(hi));
    }
    *(uint2*)((char*)&g_rhi[buf][ck][0] + boff) = ph.v;
    *(uint2*)((char*)&g_rlo[buf][ck][0] + boff) = pl.v;
}

// ---------------- main persistent kernel ----------------
__global__ void __launch_bounds__(256, 1)
rnn_kernel(
    const float* __restrict__ u0, const float* __restrict__ fs,
    const float* __restrict__ noise, const float* __restrict__ Wrec,
    const float* __restrict__ bias, float* __restrict__ out_u,
    float* __restrict__ out_du, float* __restrict__ out_eta)
{
    extern __shared__ char smem[];
    const uint32_t sbase = smem_u32(smem);
    const int tid = threadIdx.x;
    const int wid = tid >> 5;
    const int lane = tid & 31;
    const int cta = blockIdx.x;
    const int mt = cta >> 3;   // M tile 0..15
    const int kc = cta & 7;    // K chunk 0..7

    // barrier bases (own flag: equal across ALL CTAs at every launch boundary)
    const unsigned baseR = *(volatile unsigned*)&g_flagR[cta][0];
    const unsigned baseP = *(volatile unsigned*)&g_flagP[cta][0];

    // ---- eta_final copy (folded; 4KB per CTA) ----
    {
        int i = cta * (NB * NH / NCTA) + tid * 4;        // 1024 floats per CTA
        int col = i >> 11, n = i & 2047;
        float4 v = *(const float4*)(noise + (size_t)col * (TS + 1) * NH + (size_t)TS * NH + n);
        *(float4*)(out_eta + i) = v;
    }

    // ---- load + split W tile into SMEM, 8x8-blocked (once) ----
    {
        const float* wsrc = Wrec + (size_t)(mt * M_TILE) * NH + kc * K_CHUNK;
        for (int c = tid; c < M_TILE * (K_CHUNK / 8); c += 256) {   // 4096 chunks
            int row = c >> 5;
            int k0 = (c & 31) * 8;
            float4 w0 = *(const float4*)(wsrc + (size_t)row * NH + k0);
            float4 w1 = *(const float4*)(wsrc + (size_t)row * NH + k0 + 4);
            float wv[8] = {w0.x, w0.y, w0.z, w0.w, w1.x, w1.y, w1.z, w1.w};
            Pack8 ph, pl;
#pragma unroll
            for (int j = 0; j < 8; j++) {
                __nv_bfloat16 hi = __float2bfloat16(wv[j]);
                ph.h[j] = hi;
                pl.h[j] = __float2bfloat16(wv[j] - __bfloat162float(hi));
            }
            // A tile layout: tile(m>>3, k>>3) at ((m>>3)*32 + (k>>3))*128, row (m&7)*16
            uint32_t off = (uint32_t)((row >> 3) * 32 + (k0 >> 3)) * 128u + (uint32_t)(row & 7) * 16u;
            *(uint4*)(smem + OFF_AHI + off) = ph.v;
            *(uint4*)(smem + OFF_ALO + off) = pl.v;
        }
    }

    // ---- per-thread state (mapping A: col = tid/4, 4 consecutive n) ----
    const int colA = tid >> 2;
    const int n0A = mt * M_TILE + kc * 16 + (tid & 3) * 4;
    // writer-side split target: chunk + byte offset in blocked layout
    const int wck = n0A >> 8;                       // chunk 0..7
    const int wlk = n0A & 255;                      // local k (4 consecutive)
    const uint32_t wboff = (uint32_t)(((wlk >> 3) * 8 + (colA >> 3)) * 128
                                      + (colA & 7) * 16 + (wlk & 7) * 2);
    float u[4], bs[4], tinv[4];
    {
        float4 t4 = *(const float4*)(u0 + (size_t)colA * NH + n0A);
        u[0] = t4.x; u[1] = t4.y; u[2] = t4.z; u[3] = t4.w;
        float4 b4 = *(const float4*)(bias + n0A);
        bs[0] = b4.x; bs[1] = b4.y; bs[2] = b4.z; bs[3] = b4.w;
#pragma unroll
        for (int j = 0; j < 4; j++) tinv[j] = (n0A + j < NEXC) ? 50.0f : 100.0f;
    }
    write_r_split(0, wck, wboff, u);   // r(0) = relu(u0)  (split applies relu)

    arrive_r(cta, tid, baseR + 1);     // r(0) published

    // ---- per-lane ldmatrix base addresses ----
    const uint32_t aOffL = (uint32_t)((wid * 2 + ((lane >> 3) & 1)) * 4096
                                      + (lane >> 4) * 128 + (lane & 7) * 16);
    const uint32_t aAhi = sbase + OFF_AHI + aOffL;
    const uint32_t aAlo = sbase + OFF_ALO + aOffL;
    const uint32_t bOffL = (uint32_t)(((lane >> 3) & 1) * 1024
                                      + (lane >> 4) * 128 + (lane & 7) * 16);
    const uint32_t aBhi = sbase + OFF_BHI + bOffL;
    const uint32_t aBlo = sbase + OFF_BLO + bOffL;

    // per-warp B-copy mapping: warp w streams source kc*16+w (k-half 0)
    // then source kc*16+8+w (k-half 1); each source slice = 2KB hi + 2KB lo,
    // contiguous at byte offset wid*2048 (half0) / 16384 + wid*2048 (half1)
    const int src0 = kc * 16 + wid;
    const int src1 = src0 + 8;
    const uint32_t cpoff0 = (uint32_t)(wid * 2048 + lane * 16);
    const uint32_t cpoff1 = cpoff0 + 16384u;

    // ---- A-hi fragments: resident in registers for the whole run ----
    uint32_t ahreg[16][4];
#pragma unroll
    for (int ks = 0; ks < 16; ks++)
        LDSM4(ahreg[ks], aAhi + (uint32_t)ks * 256u);

    for (int t = 0; t < TS; t++) {
        const int pb = t & 1;

        // prefetch fs / noise for this step (independent of r; issue before wait)
        float4 f4 = *(const float4*)(fs + ((size_t)colA * TS + t) * NH + n0A);
        float4 e4 = *(const float4*)(noise + ((size_t)colA * (TS + 1) + t) * NH + n0A);

        const char* srcH = (const char*)&g_rhi[pb][kc][0];
        const char* srcL = (const char*)&g_rlo[pb][kc][0];
        const unsigned tgt = baseR + t + 1;

        // ---- per-warp streaming B copy: half0 source (mtile 2kc) ----
        while ((int)(ld_acq(&g_flagR[src0][0]) - tgt) < 0) { }
#pragma unroll
        for (int i = 0; i < 4; i++) {
            uint32_t o = cpoff0 + (uint32_t)i * 512u;
            CP_ASYNC16(sbase + OFF_BHI + o, srcH + o);
            CP_ASYNC16(sbase + OFF_BLO + o, srcL + o);
        }
        CP_COMMIT();

        // ---- half1 source (mtile 2kc+1) ----
        while ((int)(ld_acq(&g_flagR[src1][0]) - tgt) < 0) { }
#pragma unroll
        for (int i = 0; i < 4; i++) {
            uint32_t o = cpoff1 + (uint32_t)i * 512u;
            CP_ASYNC16(sbase + OFF_BHI + o, srcH + o);
            CP_ASYNC16(sbase + OFF_BLO + o, srcL + o);
        }
        CP_COMMIT();

        CP_WAIT1();          // half0 resident (this thread)
        __syncthreads();     // all warps' half0 resident

        // ---- GEMM: 16 k-steps, 8 n-frags, 3-pass split-bf16 (A-hi from regs) ----
        float acc[32];
#pragma unroll
        for (int i = 0; i < 32; i++) acc[i] = 0.0f;

#pragma unroll
        for (int ks = 0; ks < 8; ks++) {
            uint32_t al[4];
            LDSM4(al, aAlo + (uint32_t)ks * 256u);
#pragma unroll
            for (int nf2 = 0; nf2 < 4; nf2++) {
                uint32_t bh[4], bl[4];
                LDSM4(bh, aBhi + (uint32_t)ks * 2048u + (uint32_t)nf2 * 256u);
                LDSM4(bl, aBlo + (uint32_t)ks * 2048u + (uint32_t)nf2 * 256u);
                float* c0 = acc + (nf2 * 2) * 4;
                float* c1 = acc + (nf2 * 2 + 1) * 4;
                MMA16816(c0, ahreg[ks], bh[0], bh[1]);
                MMA16816(c1, ahreg[ks], bh[2], bh[3]);
                MMA16816(c0, ahreg[ks], bl[0], bl[1]);
                MMA16816(c1, ahreg[ks], bl[2], bl[3]);
                MMA16816(c0, al, bh[0], bh[1]);
                MMA16816(c1, al, bh[2], bh[3]);
            }
        }

        CP_WAIT0();          // half1 resident (this thread)
        __syncthreads();     // all warps' half1 resident

#pragma unroll
        for (int ks = 8; ks < 16; ks++) {
            uint32_t al[4];
            LDSM4(al, aAlo + (uint32_t)ks * 256u);
#pragma unroll
            for (int nf2 = 0; nf2 < 4; nf2++) {
                uint32_t bh[4], bl[4];
                LDSM4(bh, aBhi + (uint32_t)ks * 2048u + (uint32_t)nf2 * 256u);
                LDSM4(bl, aBlo + (uint32_t)ks * 2048u + (uint32_t)nf2 * 256u);
                float* c0 = acc + (nf2 * 2) * 4;
                float* c1 = acc + (nf2 * 2 + 1) * 4;
                MMA16816(c0, ahreg[ks], bh[0], bh[1]);
                MMA16816(c1, ahreg[ks], bh[2], bh[3]);
                MMA16816(c0, ahreg[ks], bl[0], bl[1]);
                MMA16816(c1, ahreg[ks], bl[2], bl[3]);
                MMA16816(c0, al, bh[0], bh[1]);
                MMA16816(c1, al, bh[2], bh[3]);
            }
        }

        // ---- store partials to global ----
        {
            float* pdst = g_partial + (size_t)cta * (M_TILE * NB);
            int r0 = wid * 16 + (lane >> 2);
            int cc = (lane & 3) * 2;
#pragma unroll
            for (int nf = 0; nf < 8; nf++) {
                *(float2*)(pdst + (size_t)r0 * NB + nf * 8 + cc) =
                    make_float2(acc[nf * 4 + 0], acc[nf * 4 + 1]);
                *(float2*)(pdst + (size_t)(r0 + 8) * NB + nf * 8 + cc) =
                    make_float2(acc[nf * 4 + 2], acc[nf * 4 + 3]);
            }
        }

        barrier_grp(cta, mt, tid, baseP + t + 1);   // mtile group: partials ready

        // ---- reduce 8 partials -> rec tile in SMEM ----
        {
            int mB = tid >> 4;            // 0..15 local row
            int cB = (tid & 15) * 4;      // col base
            float4 acc4 = make_float4(0.f, 0.f, 0.f, 0.f);
#pragma unroll
            for (int k2 = 0; k2 < 8; k2++) {
                float4 v = __ldcg((const float4*)(g_partial +
                    ((size_t)(mt * 8 + k2) * M_TILE + kc * 16 + mB) * NB + cB));
                acc4.x += v.x; acc4.y += v.y; acc4.z += v.z; acc4.w += v.w;
            }
            *(float4*)(smem + OFF_REC + (size_t)(mB * 68 + cB) * 4) = acc4;
        }
        __syncthreads();

        // ---- pointwise update (r split published before output stores) ----
        {
            float fv[4] = {f4.x, f4.y, f4.z, f4.w};
            float ev[4] = {e4.x, e4.y, e4.z, e4.w};
            float rec[4], du[4], un[4];
#pragma unroll
            for (int j = 0; j < 4; j++)
                rec[j] = *(const float*)(smem + OFF_REC +
                            (size_t)(((tid & 3) * 4 + j) * 68 + colA) * 4);
#pragma unroll
            for (int j = 0; j < 4; j++) {
                du[j] = (-u[j] + fv[j] + rec[j] + bs[j] + ev[j]) * tinv[j];
                un[j] = u[j] + du[j] * DTC;
                un[j] = fminf(5.0f, fmaxf(-5.0f, un[j]));
            }
            write_r_split((t + 1) & 1, wck, wboff, un);

            arrive_r(cta, tid, baseR + t + 2);   // r(t+1) published ASAP

            // deferred output stores (off the critical path)
            float* ou = out_u + ((size_t)colA * TS + t) * NH + n0A;
            float* od = out_du + ((size_t)colA * TS + t) * NH + n0A;
            *(float4*)ou = make_float4(un[0], un[1], un[2], un[3]);
            *(float4*)od = make_float4(du[0], du[1], du[2], du[3]);
            u[0] = un[0]; u[1] = un[1]; u[2] = un[2]; u[3] = un[3];
        }
    }
}

extern "C" void kernel_launch(void* const* d_in, const int* in_sizes, int n_in,
                              void* d_out, int out_size) {
    const float* u0    = (const float*)d_in[0];
    const float* fs    = (const float*)d_in[1];
    const float* noise = (const float*)d_in[2];
    const float* Wrec  = (const float*)d_in[3];
    const float* bias  = (const float*)d_in[4];
    float* out = (float*)d_out;
    float* out_u   = out;                       // 64*256*2048
    float* out_eta = out + 33554432;            // 64*2048
    float* out_du  = out + 33554432 + 131072;

    cudaFuncSetAttribute(rnn_kernel, cudaFuncAttributeMaxDynamicSharedMemorySize, SMEM_BYTES);
    rnn_kernel<<<NCTA, 256, SMEM_BYTES>>>(u0, fs, noise, Wrec, bias, out_u, out_du, out_eta);
}